// round 4
// baseline (speedup 1.0000x reference)
#include <cuda_runtime.h>
#include <math.h>
#include <float.h>

#define TT 8
#define NN 512
#define EE 64
#define HH 128
#define NC 16          // G*G
#define PP 128
#define KX 192         // E + P
#define KG 320         // KX + H

// ---------------- persistent scratch (device globals; no allocation) ----------------
__device__ float g_obs[TT * NN * 2];        // imputed observations
__device__ float g_h[2][NN * HH];           // hidden double buffer
__device__ float g_c[NN * HH];              // cell state (in-place)
__device__ float g_grid[NN * NC * HH];      // pooled grid [512][2048]  (4 MB)
__device__ float g_part[4][NN * PP];        // K-split partials of soc GEMM
__device__ float g_slot[2][NN * 2];         // decoder position ping-pong

// ---------------- K0: impute + zero state + init position slots ----------------
__global__ void k0_setup(const float* __restrict__ obs_in) {
    int gid = blockIdx.x * blockDim.x + threadIdx.x;
    int nth = gridDim.x * blockDim.x;
    for (int i = gid; i < NN * HH; i += nth) {
        g_h[0][i] = 0.f; g_h[1][i] = 0.f; g_c[i] = 0.f;
    }
    if (gid < NN) {
        int n = gid;
        unsigned fm = 0; int first = 0; int ffound = 0;
        for (int t = 0; t < TT; t++) {
            float x = obs_in[(t * NN + n) * 2];
            float y = obs_in[(t * NN + n) * 2 + 1];
            if (isfinite(x) && isfinite(y)) {
                fm |= (1u << t);
                if (!ffound) { first = t; ffound = 1; }
            }
        }
        int last = -1;
        for (int t = 0; t < TT; t++) {
            if (fm & (1u << t)) last = t;
            int take = (last >= 0) ? last : first;
            float wx = 0.f, wy = 0.f;
            if (fm) {
                wx = obs_in[(take * NN + n) * 2];
                wy = obs_in[(take * NN + n) * 2 + 1];
            }
            g_obs[(t * NN + n) * 2]     = wx;
            g_obs[(t * NN + n) * 2 + 1] = wy;
        }
        float sx = g_obs[((TT - 1) * NN + n) * 2];
        float sy = g_obs[((TT - 1) * NN + n) * 2 + 1];
        g_slot[0][n * 2] = sx; g_slot[0][n * 2 + 1] = sy;
        g_slot[1][n * 2] = sx; g_slot[1][n * 2 + 1] = sy;
    }
}

// ---------------- K1: social pooling (grid-cell max) ----------------
// 128 blocks x 128 threads; 4 agents per block. thread = h-channel.
__global__ void __launch_bounds__(128) k1_pool(int hbuf, int pos_is_slot, int pos_idx) {
    __shared__ float spos[NN * 2];
    __shared__ unsigned char scid[4 * NN];
    __shared__ float sg[4][NC * HH];

    const float* __restrict__ h_in = g_h[hbuf];
    const float* __restrict__ pos  = pos_is_slot ? g_slot[pos_idx] : (g_obs + pos_idx * NN * 2);

    int tid  = threadIdx.x;
    int base = blockIdx.x * 4;

    for (int i = tid; i < NN * 2; i += 128) spos[i] = pos[i];
    for (int i = tid; i < 4 * NC * HH; i += 128) ((float*)sg)[i] = -FLT_MAX;
    __syncthreads();

    // precompute grid-cell ids for the 4 agents vs all j
    for (int it = tid; it < 4 * NN; it += 128) {
        int a = it >> 9, j = it & (NN - 1);
        int i = base + a;
        float rx = spos[j * 2]     - spos[i * 2];
        float ry = spos[j * 2 + 1] - spos[i * 2 + 1];
        unsigned char cid = 255;
        if (j != i && fabsf(rx) <= 1.0f && fabsf(ry) <= 1.0f) {
            int gx = (int)floorf((rx + 1.0f) * 2.0f);
            int gy = (int)floorf((ry + 1.0f) * 2.0f);
            gx = min(max(gx, 0), 3); gy = min(max(gy, 0), 3);
            cid = (unsigned char)(gx * 4 + gy);
        }
        scid[it] = cid;
    }
    __syncthreads();

    #pragma unroll 4
    for (int j = 0; j < NN; j++) {
        float hv = h_in[j * HH + tid];
        #pragma unroll
        for (int a = 0; a < 4; a++) {
            int cid = scid[a * NN + j];
            if (cid != 255) {
                float* p = &sg[a][cid * HH + tid];
                *p = fmaxf(*p, hv);
            }
        }
    }
    __syncthreads();

    #pragma unroll
    for (int a = 0; a < 4; a++) {
        #pragma unroll
        for (int c = 0; c < NC; c++) {
            float v = sg[a][c * HH + tid];
            g_grid[(base + a) * (NC * HH) + c * HH + tid] = (v == -FLT_MAX) ? 0.f : v;
        }
    }
}

// ---------------- K2: soc GEMM partials: grid[512,2048] @ W_pool^T ----------------
// grid(8 M-tiles, 4 N-tiles, 4 K-splits) x 128 threads; tile 64x32, K=512; 4x4/thread.
__global__ void __launch_bounds__(128) k2_soc(const float* __restrict__ Wp) {
    __shared__ __align__(16) float sA[16][64];   // [k][agent]
    __shared__ __align__(16) float sB[16][32];   // [k][channel]

    int tid = threadIdx.x;
    int A0  = blockIdx.x * 64;
    int C0  = blockIdx.y * 32;
    int KB0 = blockIdx.z * 512;

    int ag = tid >> 3, cg = tid & 7;
    int a0 = ag * 4, c0 = cg * 4;

    float acc[4][4] = {};
    for (int kb = 0; kb < 512; kb += 16) {
        __syncthreads();
        {
            int a = tid >> 1, kh = (tid & 1) * 8;
            const float* src = &g_grid[(A0 + a) * (NC * HH) + KB0 + kb + kh];
            float4 v0 = *(const float4*)src;
            float4 v1 = *(const float4*)(src + 4);
            sA[kh + 0][a] = v0.x; sA[kh + 1][a] = v0.y; sA[kh + 2][a] = v0.z; sA[kh + 3][a] = v0.w;
            sA[kh + 4][a] = v1.x; sA[kh + 5][a] = v1.y; sA[kh + 6][a] = v1.z; sA[kh + 7][a] = v1.w;
        }
        {
            int c = tid & 31, kq = (tid >> 5) * 4;
            float4 v = *(const float4*)&Wp[(C0 + c) * (NC * HH) + KB0 + kb + kq];
            sB[kq + 0][c] = v.x; sB[kq + 1][c] = v.y; sB[kq + 2][c] = v.z; sB[kq + 3][c] = v.w;
        }
        __syncthreads();
        #pragma unroll
        for (int k = 0; k < 16; k++) {
            float4 a4 = *(const float4*)&sA[k][a0];
            float4 b4 = *(const float4*)&sB[k][c0];
            float av[4] = {a4.x, a4.y, a4.z, a4.w};
            float bv[4] = {b4.x, b4.y, b4.z, b4.w};
            #pragma unroll
            for (int i = 0; i < 4; i++)
                #pragma unroll
                for (int j = 0; j < 4; j++)
                    acc[i][j] += av[i] * bv[j];
        }
    }
    float* dst = g_part[blockIdx.z];
    #pragma unroll
    for (int i = 0; i < 4; i++) {
        float4 v = make_float4(acc[i][0], acc[i][1], acc[i][2], acc[i][3]);
        *(float4*)&dst[(A0 + a0 + i) * PP + C0 + c0] = v;
    }
}

// ---------------- K3: fused x-build + gate GEMM + LSTM pointwise ----------------
// grid(32 agent-tiles, 4 h-tiles) x 128 threads; tile 16 agents x 128 gate rows.
__global__ void __launch_bounds__(128) k3_lstm(
    int hbuf, int pos_is_slot, int pos_idx, int prev_idx,
    const float* __restrict__ W_ih, const float* __restrict__ b_ih,
    const float* __restrict__ W_hh, const float* __restrict__ b_hh,
    const float* __restrict__ Wpos, const float* __restrict__ bpos,
    const float* __restrict__ bpool)
{
    __shared__ __align__(16) float sX[KG][16];    // [k][agent]
    __shared__ __align__(16) float sB[16][128];   // [k][gate row]
    __shared__ float sG[16][132];                 // staged gates [agent][row]

    const float* __restrict__ h_in  = g_h[hbuf];
    float*       __restrict__ h_out = g_h[hbuf ^ 1];
    const float* __restrict__ pos  = pos_is_slot ? g_slot[pos_idx]  : (g_obs + pos_idx  * NN * 2);
    const float* __restrict__ prev = pos_is_slot ? g_slot[prev_idx] : (g_obs + prev_idx * NN * 2);

    int tid = threadIdx.x;
    int A0  = blockIdx.x * 16;
    int h0  = blockIdx.y * 32;

    // build x = [relu(vel@Wpos^T+b) | relu(sum(part)+bpool) | h_in]
    for (int it = tid; it < KG * 16; it += 128) {
        int a = it & 15, k = it >> 4;
        int ga = A0 + a;
        float v;
        if (k < EE) {
            float vx = pos[ga * 2]     - prev[ga * 2];
            float vy = pos[ga * 2 + 1] - prev[ga * 2 + 1];
            v = fmaxf(Wpos[k * 2] * vx + Wpos[k * 2 + 1] * vy + bpos[k], 0.f);
        } else if (k < KX) {
            int c = k - EE;
            float s = g_part[0][ga * PP + c] + g_part[1][ga * PP + c]
                    + g_part[2][ga * PP + c] + g_part[3][ga * PP + c] + bpool[c];
            v = fmaxf(s, 0.f);
        } else {
            v = h_in[ga * HH + (k - KX)];
        }
        sX[k][a] = v;
    }

    int ag = tid >> 5, rg = tid & 31;
    int a0 = ag * 4, r0 = rg * 4;
    float acc[4][4] = {};   // [agent][row]

    for (int kb = 0; kb < KG; kb += 16) {
        __syncthreads();
        {
            int r = tid;
            int grow = h0 + (r & 31) + ((r >> 5) * HH);
            const float* srcp = (kb < KX) ? &W_ih[grow * KX + kb]
                                          : &W_hh[grow * HH + (kb - KX)];
            #pragma unroll
            for (int q = 0; q < 4; q++) {
                float4 v = *(const float4*)(srcp + q * 4);
                sB[q * 4 + 0][r] = v.x; sB[q * 4 + 1][r] = v.y;
                sB[q * 4 + 2][r] = v.z; sB[q * 4 + 3][r] = v.w;
            }
        }
        __syncthreads();
        #pragma unroll
        for (int k = 0; k < 16; k++) {
            float4 a4 = *(const float4*)&sX[kb + k][a0];
            float4 b4 = *(const float4*)&sB[k][r0];
            float av[4] = {a4.x, a4.y, a4.z, a4.w};
            float bv[4] = {b4.x, b4.y, b4.z, b4.w};
            #pragma unroll
            for (int i = 0; i < 4; i++)
                #pragma unroll
                for (int j = 0; j < 4; j++)
                    acc[i][j] += av[i] * bv[j];
        }
    }

    // add biases, stage gates
    #pragma unroll
    for (int j = 0; j < 4; j++) {
        int r = r0 + j;
        int grow = h0 + (r & 31) + ((r >> 5) * HH);
        float bias = b_ih[grow] + b_hh[grow];
        #pragma unroll
        for (int i = 0; i < 4; i++)
            sG[a0 + i][r] = acc[i][j] + bias;
    }
    __syncthreads();

    // LSTM pointwise: thread -> (hc = tid&31), agents {tid>>5, +4, +8, +12}
    int hc = tid & 31;
    #pragma unroll
    for (int q = 0; q < 4; q++) {
        int a  = (tid >> 5) + q * 4;
        int ga = A0 + a;
        float iv = sG[a][hc],      fv = sG[a][32 + hc];
        float gv = sG[a][64 + hc], ov = sG[a][96 + hc];
        int idx = ga * HH + h0 + hc;
        float c_old = g_c[idx];
        float si = 1.f / (1.f + expf(-iv));
        float sf = 1.f / (1.f + expf(-fv));
        float so = 1.f / (1.f + expf(-ov));
        float cn = sf * c_old + si * tanhf(gv);
        float hn = so * tanhf(cn);
        g_c[idx]   = cn;
        h_out[idx] = hn;
    }
}

// ---------------- K4: decoder output projection + position advance ----------------
__global__ void __launch_bounds__(256) k4_out(
    int hbuf_new, int s, float* __restrict__ out,
    const float* __restrict__ Wout, const float* __restrict__ bout)
{
    int gid = blockIdx.x * 256 + threadIdx.x;        // 0..1023
    int agent = gid >> 1, coord = gid & 1;
    const float* __restrict__ h_new = g_h[hbuf_new];
    const float* __restrict__ pos_cur = g_slot[s & 1];
    float* __restrict__ slot_next = g_slot[(s + 1) & 1];

    const float4* h4 = (const float4*)&h_new[agent * HH];
    const float4* w4 = (const float4*)&Wout[coord * HH];
    float acc = 0.f;
    #pragma unroll
    for (int k = 0; k < HH / 4; k++) {
        float4 a = h4[k], b = w4[k];
        acc += a.x * b.x + a.y * b.y + a.z * b.z + a.w * b.w;
    }
    float v = pos_cur[agent * 2 + coord] + acc + bout[coord];
    slot_next[agent * 2 + coord] = v;
    out[(s * NN + agent) * 2 + coord] = v;
}

// ---------------- host launcher ----------------
extern "C" void kernel_launch(void* const* d_in, const int* in_sizes, int n_in,
                              void* d_out, int out_size) {
    const float* obs   = (const float*)d_in[0];
    const float* Wposw = (const float*)d_in[1];
    const float* bposw = (const float*)d_in[2];
    const float* Wpool = (const float*)d_in[3];
    const float* bpool = (const float*)d_in[4];
    const float* Wihe  = (const float*)d_in[5];
    const float* bihe  = (const float*)d_in[6];
    const float* Whhe  = (const float*)d_in[7];
    const float* bhhe  = (const float*)d_in[8];
    const float* Wihd  = (const float*)d_in[9];
    const float* bihd  = (const float*)d_in[10];
    const float* Whhd  = (const float*)d_in[11];
    const float* Whhd_b= (const float*)d_in[12];
    const float* Woutw = (const float*)d_in[13];
    const float* boutw = (const float*)d_in[14];
    const float* bhhd  = Whhd_b;
    float* out = (float*)d_out;
    int np = out_size / (NN * 2);

    k0_setup<<<256, 256>>>(obs);

    int q = 0;
    // encoder: t = 1..7, pos = obs[t], prev = obs[t-1]
    for (int t = 1; t < TT; t++, q++) {
        int hb = q & 1;
        k1_pool<<<128, 128>>>(hb, 0, t);
        k2_soc<<<dim3(8, 4, 4), 128>>>(Wpool);
        k3_lstm<<<dim3(32, 4), 128>>>(hb, 0, t, t - 1,
                                      Wihe, bihe, Whhe, bhhe, Wposw, bposw, bpool);
    }
    // decoder: s = 0..np-1, pos = slot[s&1], prev = slot[(s+1)&1]
    for (int s = 0; s < np; s++, q++) {
        int hb = q & 1;
        k1_pool<<<128, 128>>>(hb, 1, s & 1);
        k2_soc<<<dim3(8, 4, 4), 128>>>(Wpool);
        k3_lstm<<<dim3(32, 4), 128>>>(hb, 1, s & 1, (s + 1) & 1,
                                      Wihd, bihd, Whhd, bhhd, Wposw, bposw, bpool);
        k4_out<<<4, 256>>>(hb ^ 1, s, out, Woutw, boutw);
    }
    (void)in_sizes; (void)n_in;
}

// round 5
// speedup vs baseline: 1.5778x; 1.5778x over previous
#include <cuda_runtime.h>
#include <math.h>
#include <float.h>

#define TT 8
#define NN 512
#define EE 64
#define HH 128
#define NC 16          // G*G
#define PP 128
#define KX 192         // E + P
#define KG 320         // KX + H

// ---------------- persistent scratch (device globals; no allocation) ----------------
__device__ float g_obs[TT * NN * 2];        // imputed observations
__device__ float g_h[2][NN * HH];           // hidden double buffer
__device__ float g_c[NN * HH];              // cell state (in-place)
__device__ float g_grid[NN * NC * HH];      // pooled grid [512][2048]
__device__ float g_part[4][NN * PP];        // K-split partials of soc GEMM
__device__ float g_slot[2][NN * 2];         // decoder position ping-pong

// ---------------- K0: impute + zero state + init position slots ----------------
__global__ void k0_setup(const float* __restrict__ obs_in) {
    int gid = blockIdx.x * blockDim.x + threadIdx.x;
    int nth = gridDim.x * blockDim.x;
    for (int i = gid; i < NN * HH; i += nth) {
        g_h[0][i] = 0.f; g_h[1][i] = 0.f; g_c[i] = 0.f;
    }
    if (gid < NN) {
        int n = gid;
        unsigned fm = 0; int first = 0; int ffound = 0;
        for (int t = 0; t < TT; t++) {
            float x = obs_in[(t * NN + n) * 2];
            float y = obs_in[(t * NN + n) * 2 + 1];
            if (isfinite(x) && isfinite(y)) {
                fm |= (1u << t);
                if (!ffound) { first = t; ffound = 1; }
            }
        }
        int last = -1;
        for (int t = 0; t < TT; t++) {
            if (fm & (1u << t)) last = t;
            int take = (last >= 0) ? last : first;
            float wx = 0.f, wy = 0.f;
            if (fm) {
                wx = obs_in[(take * NN + n) * 2];
                wy = obs_in[(take * NN + n) * 2 + 1];
            }
            g_obs[(t * NN + n) * 2]     = wx;
            g_obs[(t * NN + n) * 2 + 1] = wy;
        }
        float sx = g_obs[((TT - 1) * NN + n) * 2];
        float sy = g_obs[((TT - 1) * NN + n) * 2 + 1];
        g_slot[0][n * 2] = sx; g_slot[0][n * 2 + 1] = sy;
        g_slot[1][n * 2] = sx; g_slot[1][n * 2 + 1] = sy;
    }
}

// ---------------- K1: social pooling (grid-cell max), software-pipelined ----------------
// 128 blocks x 128 threads; 4 agents per block; thread = h-channel.
__global__ void __launch_bounds__(128) k1_pool(int hbuf, int pos_is_slot, int pos_idx) {
    __shared__ float spos[NN * 2];
    __shared__ unsigned char scid[NN * 4];     // [j][a] packed
    __shared__ float sg[4][NC * HH];           // 32KB

    const float* __restrict__ h_in = g_h[hbuf];
    const float* __restrict__ pos  = pos_is_slot ? g_slot[pos_idx] : (g_obs + pos_idx * NN * 2);

    int tid  = threadIdx.x;
    int base = blockIdx.x * 4;

    for (int i = tid; i < NN * 2; i += 128) spos[i] = pos[i];
    for (int i = tid; i < 4 * NC * HH; i += 128) ((float*)sg)[i] = -FLT_MAX;
    __syncthreads();

    // cell ids: scid[j*4 + a]
    for (int it = tid; it < NN * 4; it += 128) {
        int a = it & 3, j = it >> 2;
        int i = base + a;
        float rx = spos[j * 2]     - spos[i * 2];
        float ry = spos[j * 2 + 1] - spos[i * 2 + 1];
        unsigned char cid = 255;
        if (j != i && fabsf(rx) <= 1.0f && fabsf(ry) <= 1.0f) {
            int gx = (int)floorf((rx + 1.0f) * 2.0f);
            int gy = (int)floorf((ry + 1.0f) * 2.0f);
            gx = min(max(gx, 0), 3); gy = min(max(gy, 0), 3);
            cid = (unsigned char)(gx * 4 + gy);
        }
        scid[it] = cid;
    }
    __syncthreads();

    const uchar4* sc4 = (const uchar4*)scid;
    float bufA[8], bufB[8];
    #pragma unroll
    for (int q = 0; q < 8; q++) bufA[q] = h_in[q * HH + tid];

    for (int jb = 0; jb < NN; jb += 8) {
        // prefetch next batch (wraparound on final batch: harmless extra loads)
        #pragma unroll
        for (int q = 0; q < 8; q++)
            bufB[q] = h_in[(((jb + 8 + q) & (NN - 1)) * HH) + tid];
        #pragma unroll
        for (int q = 0; q < 8; q++) {
            uchar4 c4 = sc4[jb + q];
            float hv = bufA[q];
            if (c4.x != 255) { float* p = &sg[0][c4.x * HH + tid]; *p = fmaxf(*p, hv); }
            if (c4.y != 255) { float* p = &sg[1][c4.y * HH + tid]; *p = fmaxf(*p, hv); }
            if (c4.z != 255) { float* p = &sg[2][c4.z * HH + tid]; *p = fmaxf(*p, hv); }
            if (c4.w != 255) { float* p = &sg[3][c4.w * HH + tid]; *p = fmaxf(*p, hv); }
        }
        #pragma unroll
        for (int q = 0; q < 8; q++) bufA[q] = bufB[q];
    }
    __syncthreads();

    #pragma unroll
    for (int a = 0; a < 4; a++) {
        #pragma unroll
        for (int c = 0; c < NC; c++) {
            float v = sg[a][c * HH + tid];
            g_grid[(base + a) * (NC * HH) + c * HH + tid] = (v == -FLT_MAX) ? 0.f : v;
        }
    }
}

// ---------------- K2: soc GEMM partials: grid[512,2048] @ W_pool^T ----------------
// grid(8 M, 4 N, 4 Ksplit) x 256 threads; tile 64x32, K=512/split; double-buffered.
__global__ void __launch_bounds__(256) k2_soc(const float* __restrict__ Wp) {
    __shared__ __align__(16) float sA[2][16][64];
    __shared__ __align__(16) float sB[2][16][32];

    int tid = threadIdx.x;
    int A0  = blockIdx.x * 64;
    int C0  = blockIdx.y * 32;
    int KB0 = blockIdx.z * 512;

    int la = tid >> 2;              // 0..63 (A row) / 0..31 (B row for tid<128)
    int lk = (tid & 3) * 4;         // k sub-offset
    const float* Asrc = &g_grid[(A0 + la) * (NC * HH) + KB0 + lk];
    const float* Bsrc = &Wp[(C0 + la) * (NC * HH) + KB0 + lk];   // valid only tid<128

    int a0 = (tid >> 4) * 4;        // 4 agents
    int c0 = (tid & 15) * 2;        // 2 channels

    float4 ra = *(const float4*)Asrc;
    float4 rb = make_float4(0.f, 0.f, 0.f, 0.f);
    if (tid < 128) rb = *(const float4*)Bsrc;

    sA[0][lk + 0][la] = ra.x; sA[0][lk + 1][la] = ra.y;
    sA[0][lk + 2][la] = ra.z; sA[0][lk + 3][la] = ra.w;
    if (tid < 128) {
        sB[0][lk + 0][la] = rb.x; sB[0][lk + 1][la] = rb.y;
        sB[0][lk + 2][la] = rb.z; sB[0][lk + 3][la] = rb.w;
    }
    ra = *(const float4*)(Asrc + 16);
    if (tid < 128) rb = *(const float4*)(Bsrc + 16);
    __syncthreads();

    float acc[4][2] = {};
    for (int kc = 0; kc < 32; kc++) {
        int cur = kc & 1;
        if (kc + 1 < 32) {
            int nb = cur ^ 1;
            sA[nb][lk + 0][la] = ra.x; sA[nb][lk + 1][la] = ra.y;
            sA[nb][lk + 2][la] = ra.z; sA[nb][lk + 3][la] = ra.w;
            if (tid < 128) {
                sB[nb][lk + 0][la] = rb.x; sB[nb][lk + 1][la] = rb.y;
                sB[nb][lk + 2][la] = rb.z; sB[nb][lk + 3][la] = rb.w;
            }
        }
        if (kc + 2 < 32) {
            ra = *(const float4*)(Asrc + (kc + 2) * 16);
            if (tid < 128) rb = *(const float4*)(Bsrc + (kc + 2) * 16);
        }
        #pragma unroll
        for (int k = 0; k < 16; k++) {
            float4 a4 = *(const float4*)&sA[cur][k][a0];
            float2 b2 = *(const float2*)&sB[cur][k][c0];
            acc[0][0] += a4.x * b2.x; acc[0][1] += a4.x * b2.y;
            acc[1][0] += a4.y * b2.x; acc[1][1] += a4.y * b2.y;
            acc[2][0] += a4.z * b2.x; acc[2][1] += a4.z * b2.y;
            acc[3][0] += a4.w * b2.x; acc[3][1] += a4.w * b2.y;
        }
        __syncthreads();
    }

    float* dst = g_part[blockIdx.z];
    #pragma unroll
    for (int i = 0; i < 4; i++) {
        float2 v = make_float2(acc[i][0], acc[i][1]);
        *(float2*)&dst[(A0 + a0 + i) * PP + C0 + c0] = v;
    }
}

// ---------------- K3: fused x-build + gate GEMM + LSTM pointwise ----------------
// grid(32 agent-tiles, 4 h-tiles) x 256 threads; 16 agents x 128 gate rows; double-buffered.
__global__ void __launch_bounds__(256) k3_lstm(
    int hbuf, int pos_is_slot, int pos_idx, int prev_idx,
    const float* __restrict__ W_ih, const float* __restrict__ b_ih,
    const float* __restrict__ W_hh, const float* __restrict__ b_hh,
    const float* __restrict__ Wpos, const float* __restrict__ bpos,
    const float* __restrict__ bpool)
{
    __shared__ __align__(16) float sX[KG][16];       // [k][agent]  20KB
    __shared__ __align__(16) float sB[2][16][128];   // [k][row]    16KB
    __shared__ float sG[16][132];                    // gates       8.4KB

    const float* __restrict__ h_in  = g_h[hbuf];
    float*       __restrict__ h_out = g_h[hbuf ^ 1];
    const float* __restrict__ pos  = pos_is_slot ? g_slot[pos_idx]  : (g_obs + pos_idx  * NN * 2);
    const float* __restrict__ prev = pos_is_slot ? g_slot[prev_idx] : (g_obs + prev_idx * NN * 2);

    int tid = threadIdx.x;
    int A0  = blockIdx.x * 16;
    int h0  = blockIdx.y * 32;

    // build x = [relu(vel@Wpos^T+b) | relu(sum(part)+bpool) | h_in] (k-coalesced)
    for (int it = tid; it < 16 * KG; it += 256) {
        int a = it / KG, k = it - a * KG;
        int ga = A0 + a;
        float v;
        if (k < EE) {
            float vx = pos[ga * 2]     - prev[ga * 2];
            float vy = pos[ga * 2 + 1] - prev[ga * 2 + 1];
            v = fmaxf(Wpos[k * 2] * vx + Wpos[k * 2 + 1] * vy + bpos[k], 0.f);
        } else if (k < KX) {
            int c = k - EE;
            v = fmaxf(g_part[0][ga * PP + c] + g_part[1][ga * PP + c]
                    + g_part[2][ga * PP + c] + g_part[3][ga * PP + c] + bpool[c], 0.f);
        } else {
            v = h_in[ga * HH + (k - KX)];
        }
        sX[k][a] = v;
    }

    // weight loads: 128 rows x 16k per chunk; thread covers (row rr, k-half kh)
    int rr = tid & 127;
    int kh = (tid >> 7) * 8;
    int grow = h0 + (rr & 31) + ((rr >> 5) * HH);
    const float* ihp = W_ih + grow * KX + kh;
    const float* hhp = W_hh + grow * HH + kh;

    float4 p0, p1;
    p0 = *(const float4*)ihp; p1 = *(const float4*)(ihp + 4);
    sB[0][kh + 0][rr] = p0.x; sB[0][kh + 1][rr] = p0.y; sB[0][kh + 2][rr] = p0.z; sB[0][kh + 3][rr] = p0.w;
    sB[0][kh + 4][rr] = p1.x; sB[0][kh + 5][rr] = p1.y; sB[0][kh + 6][rr] = p1.z; sB[0][kh + 7][rr] = p1.w;
    p0 = *(const float4*)(ihp + 16); p1 = *(const float4*)(ihp + 20);
    __syncthreads();

    int a0 = (tid >> 5) * 2;
    int r0 = (tid & 31) * 4;
    float acc[2][4] = {};

    for (int kc = 0; kc < 20; kc++) {
        int cur = kc & 1;
        if (kc + 1 < 20) {
            int nb = cur ^ 1;
            sB[nb][kh + 0][rr] = p0.x; sB[nb][kh + 1][rr] = p0.y; sB[nb][kh + 2][rr] = p0.z; sB[nb][kh + 3][rr] = p0.w;
            sB[nb][kh + 4][rr] = p1.x; sB[nb][kh + 5][rr] = p1.y; sB[nb][kh + 6][rr] = p1.z; sB[nb][kh + 7][rr] = p1.w;
        }
        if (kc + 2 < 20) {
            int c2 = kc + 2;
            const float* sp = (c2 < 12) ? (ihp + c2 * 16) : (hhp + (c2 - 12) * 16);
            p0 = *(const float4*)sp; p1 = *(const float4*)(sp + 4);
        }
        #pragma unroll
        for (int k = 0; k < 16; k++) {
            float2 a2 = *(const float2*)&sX[kc * 16 + k][a0];
            float4 b4 = *(const float4*)&sB[cur][k][r0];
            acc[0][0] += a2.x * b4.x; acc[0][1] += a2.x * b4.y;
            acc[0][2] += a2.x * b4.z; acc[0][3] += a2.x * b4.w;
            acc[1][0] += a2.y * b4.x; acc[1][1] += a2.y * b4.y;
            acc[1][2] += a2.y * b4.z; acc[1][3] += a2.y * b4.w;
        }
        __syncthreads();
    }

    // biases + stage gates
    #pragma unroll
    for (int j = 0; j < 4; j++) {
        int r = r0 + j;
        int gr2 = h0 + (r & 31) + ((r >> 5) * HH);
        float bias = b_ih[gr2] + b_hh[gr2];
        sG[a0 + 0][r] = acc[0][j] + bias;
        sG[a0 + 1][r] = acc[1][j] + bias;
    }
    __syncthreads();

    // LSTM pointwise
    int hc = tid & 31;
    #pragma unroll
    for (int q = 0; q < 2; q++) {
        int a  = (tid >> 5) + q * 8;
        int ga = A0 + a;
        float iv = sG[a][hc],      fv = sG[a][32 + hc];
        float gv = sG[a][64 + hc], ov = sG[a][96 + hc];
        int idx = ga * HH + h0 + hc;
        float c_old = g_c[idx];
        float si = 1.f / (1.f + __expf(-iv));
        float sf = 1.f / (1.f + __expf(-fv));
        float so = 1.f / (1.f + __expf(-ov));
        float cn = sf * c_old + si * tanhf(gv);
        float hn = so * tanhf(cn);
        g_c[idx]   = cn;
        h_out[idx] = hn;
    }
}

// ---------------- K4: decoder output projection + position advance ----------------
__global__ void __launch_bounds__(256) k4_out(
    int hbuf_new, int s, float* __restrict__ out,
    const float* __restrict__ Wout, const float* __restrict__ bout)
{
    int gid = blockIdx.x * 256 + threadIdx.x;        // 0..1023
    int agent = gid >> 1, coord = gid & 1;
    const float* __restrict__ h_new = g_h[hbuf_new];
    const float* __restrict__ pos_cur = g_slot[s & 1];
    float* __restrict__ slot_next = g_slot[(s + 1) & 1];

    const float4* h4 = (const float4*)&h_new[agent * HH];
    const float4* w4 = (const float4*)&Wout[coord * HH];
    float acc = 0.f;
    #pragma unroll
    for (int k = 0; k < HH / 4; k++) {
        float4 a = h4[k], b = w4[k];
        acc += a.x * b.x + a.y * b.y + a.z * b.z + a.w * b.w;
    }
    float v = pos_cur[agent * 2 + coord] + acc + bout[coord];
    slot_next[agent * 2 + coord] = v;
    out[(s * NN + agent) * 2 + coord] = v;
}

// ---------------- host launcher ----------------
extern "C" void kernel_launch(void* const* d_in, const int* in_sizes, int n_in,
                              void* d_out, int out_size) {
    const float* obs   = (const float*)d_in[0];
    const float* Wposw = (const float*)d_in[1];
    const float* bposw = (const float*)d_in[2];
    const float* Wpool = (const float*)d_in[3];
    const float* bpool = (const float*)d_in[4];
    const float* Wihe  = (const float*)d_in[5];
    const float* bihe  = (const float*)d_in[6];
    const float* Whhe  = (const float*)d_in[7];
    const float* bhhe  = (const float*)d_in[8];
    const float* Wihd  = (const float*)d_in[9];
    const float* bihd  = (const float*)d_in[10];
    const float* Whhd  = (const float*)d_in[11];
    const float* bhhd  = (const float*)d_in[12];
    const float* Woutw = (const float*)d_in[13];
    const float* boutw = (const float*)d_in[14];
    float* out = (float*)d_out;
    int np = out_size / (NN * 2);

    k0_setup<<<256, 256>>>(obs);

    int q = 0;
    // encoder: t = 1..7, pos = obs[t], prev = obs[t-1]
    for (int t = 1; t < TT; t++, q++) {
        int hb = q & 1;
        k1_pool<<<128, 128>>>(hb, 0, t);
        k2_soc<<<dim3(8, 4, 4), 256>>>(Wpool);
        k3_lstm<<<dim3(32, 4), 256>>>(hb, 0, t, t - 1,
                                      Wihe, bihe, Whhe, bhhe, Wposw, bposw, bpool);
    }
    // decoder: s = 0..np-1, pos = slot[s&1], prev = slot[(s+1)&1]
    for (int s = 0; s < np; s++, q++) {
        int hb = q & 1;
        k1_pool<<<128, 128>>>(hb, 1, s & 1);
        k2_soc<<<dim3(8, 4, 4), 256>>>(Wpool);
        k3_lstm<<<dim3(32, 4), 256>>>(hb, 1, s & 1, (s + 1) & 1,
                                      Wihd, bihd, Whhd, bhhd, Wposw, bposw, bpool);
        k4_out<<<4, 256>>>(hb ^ 1, s, out, Woutw, boutw);
    }
    (void)in_sizes; (void)n_in;
}

// round 6
// speedup vs baseline: 1.9901x; 1.2613x over previous
#include <cuda_runtime.h>
#include <math.h>
#include <float.h>

#define TT 8
#define NN 512
#define EE 64
#define HH 128
#define NC 16          // G*G
#define PP 128
#define KX 192         // E + P
#define KG 320         // KX + H
#define KSP 8          // K-splits for soc GEMM

// ---------------- persistent scratch (device globals; no allocation) ----------------
__device__ float g_obs[TT * NN * 2];        // imputed observations
__device__ float g_h[2][NN * HH];           // hidden double buffer
__device__ float g_c[NN * HH];              // cell state (in-place)
__device__ float g_grid[NN * NC * HH];      // pooled grid [512][2048]
__device__ float g_part[KSP][NN * PP];      // K-split partials of soc GEMM
__device__ float g_slot[2][NN * 2];         // decoder position ping-pong

// ---------------- K0: impute + zero state + init position slots ----------------
__global__ void k0_setup(const float* __restrict__ obs_in) {
    int gid = blockIdx.x * blockDim.x + threadIdx.x;
    int nth = gridDim.x * blockDim.x;
    for (int i = gid; i < NN * HH; i += nth) {
        g_h[0][i] = 0.f; g_h[1][i] = 0.f; g_c[i] = 0.f;
    }
    if (gid < NN) {
        int n = gid;
        unsigned fm = 0; int first = 0; int ffound = 0;
        for (int t = 0; t < TT; t++) {
            float x = obs_in[(t * NN + n) * 2];
            float y = obs_in[(t * NN + n) * 2 + 1];
            if (isfinite(x) && isfinite(y)) {
                fm |= (1u << t);
                if (!ffound) { first = t; ffound = 1; }
            }
        }
        int last = -1;
        for (int t = 0; t < TT; t++) {
            if (fm & (1u << t)) last = t;
            int take = (last >= 0) ? last : first;
            float wx = 0.f, wy = 0.f;
            if (fm) {
                wx = obs_in[(take * NN + n) * 2];
                wy = obs_in[(take * NN + n) * 2 + 1];
            }
            g_obs[(t * NN + n) * 2]     = wx;
            g_obs[(t * NN + n) * 2 + 1] = wy;
        }
        float sx = g_obs[((TT - 1) * NN + n) * 2];
        float sy = g_obs[((TT - 1) * NN + n) * 2 + 1];
        g_slot[0][n * 2] = sx; g_slot[0][n * 2 + 1] = sy;
        g_slot[1][n * 2] = sx; g_slot[1][n * 2 + 1] = sy;
    }
}

// ---------------- K1: social pooling (grid-cell max) ----------------
// 256 blocks x 128 threads; 2 agents per block; thread = h-channel.
__global__ void __launch_bounds__(128) k1_pool(int hbuf, int pos_is_slot, int pos_idx) {
    __shared__ float spos[NN * 2];
    __shared__ unsigned char scid[NN * 2];     // [j][a]
    __shared__ float sg[2][NC * HH];           // 16KB

    const float* __restrict__ h_in = g_h[hbuf];
    const float* __restrict__ pos  = pos_is_slot ? g_slot[pos_idx] : (g_obs + pos_idx * NN * 2);

    int tid  = threadIdx.x;
    int base = blockIdx.x * 2;

    for (int i = tid; i < NN * 2; i += 128) spos[i] = pos[i];
    for (int i = tid; i < 2 * NC * HH; i += 128) ((float*)sg)[i] = -FLT_MAX;
    __syncthreads();

    for (int it = tid; it < NN * 2; it += 128) {
        int a = it & 1, j = it >> 1;
        int i = base + a;
        float rx = spos[j * 2]     - spos[i * 2];
        float ry = spos[j * 2 + 1] - spos[i * 2 + 1];
        unsigned char cid = 255;
        if (j != i && fabsf(rx) <= 1.0f && fabsf(ry) <= 1.0f) {
            int gx = (int)floorf((rx + 1.0f) * 2.0f);
            int gy = (int)floorf((ry + 1.0f) * 2.0f);
            gx = min(max(gx, 0), 3); gy = min(max(gy, 0), 3);
            cid = (unsigned char)(gx * 4 + gy);
        }
        scid[it] = cid;
    }
    __syncthreads();

    const uchar2* sc2 = (const uchar2*)scid;
    float bufA[8], bufB[8];
    #pragma unroll
    for (int q = 0; q < 8; q++) bufA[q] = h_in[q * HH + tid];

    for (int jb = 0; jb < NN; jb += 8) {
        #pragma unroll
        for (int q = 0; q < 8; q++)
            bufB[q] = h_in[(((jb + 8 + q) & (NN - 1)) * HH) + tid];
        #pragma unroll
        for (int q = 0; q < 8; q++) {
            uchar2 c2 = sc2[jb + q];
            float hv = bufA[q];
            if (c2.x != 255) { float* p = &sg[0][c2.x * HH + tid]; *p = fmaxf(*p, hv); }
            if (c2.y != 255) { float* p = &sg[1][c2.y * HH + tid]; *p = fmaxf(*p, hv); }
        }
        #pragma unroll
        for (int q = 0; q < 8; q++) bufA[q] = bufB[q];
    }
    __syncthreads();

    #pragma unroll
    for (int a = 0; a < 2; a++) {
        #pragma unroll
        for (int c = 0; c < NC; c++) {
            float v = sg[a][c * HH + tid];
            g_grid[(base + a) * (NC * HH) + c * HH + tid] = (v == -FLT_MAX) ? 0.f : v;
        }
    }
}

// ---------------- K2: soc GEMM partials: grid[512,2048] @ W_pool^T ----------------
// grid(8 M, 4 N, 8 Ksplit) = 256 blocks x 256 threads; tile 64x32, K=256/split.
// A in smem row-major [agent][k] (conflict-free); B k-major [k][channel].
__global__ void __launch_bounds__(256) k2_soc(const float* __restrict__ Wp) {
    __shared__ __align__(16) float sA[2][64][36];   // row-major, padded
    __shared__ __align__(16) float sB[2][32][34];   // k-major, padded

    int tid = threadIdx.x;
    int A0  = blockIdx.x * 64;
    int C0  = blockIdx.y * 32;
    int KB0 = blockIdx.z * 256;

    int la  = tid >> 2;          // 0..63 agent row
    int lka = (tid & 3) * 8;     // k offset within 32-chunk
    int cb  = tid >> 3;          // 0..31 channel row
    int lkb = (tid & 7) * 4;

    const float* Asrc = &g_grid[(A0 + la) * (NC * HH) + KB0 + lka];
    const float* Bsrc = &Wp[(C0 + cb) * (NC * HH) + KB0 + lkb];

    int a0 = (tid >> 4) * 4;     // 4 agents
    int c0 = (tid & 15) * 2;     // 2 channels

    float4 ra0 = *(const float4*)Asrc;
    float4 ra1 = *(const float4*)(Asrc + 4);
    float4 rb  = *(const float4*)Bsrc;

    ((float4*)&sA[0][la][lka])[0] = ra0;
    ((float4*)&sA[0][la][lka])[1] = ra1;
    sB[0][lkb + 0][cb] = rb.x; sB[0][lkb + 1][cb] = rb.y;
    sB[0][lkb + 2][cb] = rb.z; sB[0][lkb + 3][cb] = rb.w;

    ra0 = *(const float4*)(Asrc + 32);
    ra1 = *(const float4*)(Asrc + 36);
    rb  = *(const float4*)(Bsrc + 32);
    __syncthreads();

    float acc[4][2] = {};
    for (int kc = 0; kc < 8; kc++) {
        int cur = kc & 1;
        if (kc + 1 < 8) {
            int nb = cur ^ 1;
            ((float4*)&sA[nb][la][lka])[0] = ra0;
            ((float4*)&sA[nb][la][lka])[1] = ra1;
            sB[nb][lkb + 0][cb] = rb.x; sB[nb][lkb + 1][cb] = rb.y;
            sB[nb][lkb + 2][cb] = rb.z; sB[nb][lkb + 3][cb] = rb.w;
        }
        if (kc + 2 < 8) {
            ra0 = *(const float4*)(Asrc + (kc + 2) * 32);
            ra1 = *(const float4*)(Asrc + (kc + 2) * 32 + 4);
            rb  = *(const float4*)(Bsrc + (kc + 2) * 32);
        }
        // inner 32 k with 2-stage register pipeline
        float av0 = sA[cur][a0 + 0][0], av1 = sA[cur][a0 + 1][0];
        float av2 = sA[cur][a0 + 2][0], av3 = sA[cur][a0 + 3][0];
        float2 bv = *(const float2*)&sB[cur][0][c0];
        #pragma unroll
        for (int k = 0; k < 32; k++) {
            float an0, an1, an2, an3; float2 bn;
            if (k < 31) {
                an0 = sA[cur][a0 + 0][k + 1]; an1 = sA[cur][a0 + 1][k + 1];
                an2 = sA[cur][a0 + 2][k + 1]; an3 = sA[cur][a0 + 3][k + 1];
                bn  = *(const float2*)&sB[cur][k + 1][c0];
            }
            acc[0][0] += av0 * bv.x; acc[0][1] += av0 * bv.y;
            acc[1][0] += av1 * bv.x; acc[1][1] += av1 * bv.y;
            acc[2][0] += av2 * bv.x; acc[2][1] += av2 * bv.y;
            acc[3][0] += av3 * bv.x; acc[3][1] += av3 * bv.y;
            if (k < 31) { av0 = an0; av1 = an1; av2 = an2; av3 = an3; bv = bn; }
        }
        __syncthreads();
    }

    float* dst = g_part[blockIdx.z];
    #pragma unroll
    for (int i = 0; i < 4; i++) {
        float2 v = make_float2(acc[i][0], acc[i][1]);
        *(float2*)&dst[(A0 + a0 + i) * PP + C0 + c0] = v;
    }
}

// ---------------- K3: fused x-build + gate GEMM + LSTM pointwise ----------------
// grid(32 agent-tiles, 4 h-tiles) x 256 threads; 16 agents x 128 gate rows.
__global__ void __launch_bounds__(256) k3_lstm(
    int hbuf, int pos_is_slot, int pos_idx, int prev_idx,
    const float* __restrict__ W_ih, const float* __restrict__ b_ih,
    const float* __restrict__ W_hh, const float* __restrict__ b_hh,
    const float* __restrict__ Wpos, const float* __restrict__ bpos,
    const float* __restrict__ bpool)
{
    __shared__ __align__(16) float sX[KG][16];       // [k][agent]  20KB
    __shared__ __align__(16) float sB[2][16][128];   // [k][row]    16KB
    __shared__ float sG[16][132];                    // gates       8.4KB

    const float* __restrict__ h_in  = g_h[hbuf];
    float*       __restrict__ h_out = g_h[hbuf ^ 1];
    const float* __restrict__ pos  = pos_is_slot ? g_slot[pos_idx]  : (g_obs + pos_idx  * NN * 2);
    const float* __restrict__ prev = pos_is_slot ? g_slot[prev_idx] : (g_obs + prev_idx * NN * 2);

    int tid = threadIdx.x;
    int A0  = blockIdx.x * 16;
    int h0  = blockIdx.y * 32;

    // build x = [relu(vel@Wpos^T+b) | relu(sum(part)+bpool) | h_in]
    for (int it = tid; it < 16 * KG; it += 256) {
        int a = it / KG, k = it - a * KG;
        int ga = A0 + a;
        float v;
        if (k < EE) {
            float vx = pos[ga * 2]     - prev[ga * 2];
            float vy = pos[ga * 2 + 1] - prev[ga * 2 + 1];
            v = fmaxf(Wpos[k * 2] * vx + Wpos[k * 2 + 1] * vy + bpos[k], 0.f);
        } else if (k < KX) {
            int c = k - EE;
            float s = bpool[c];
            #pragma unroll
            for (int p = 0; p < KSP; p++) s += g_part[p][ga * PP + c];
            v = fmaxf(s, 0.f);
        } else {
            v = h_in[ga * HH + (k - KX)];
        }
        sX[k][a] = v;
    }

    // weight loads: 128 rows x 16k per chunk; thread covers (row rr, k-half kh)
    int rr = tid & 127;
    int kh = (tid >> 7) * 8;
    int grow = h0 + (rr & 31) + ((rr >> 5) * HH);
    const float* ihp = W_ih + grow * KX + kh;
    const float* hhp = W_hh + grow * HH + kh;

    float4 p0, p1;
    p0 = *(const float4*)ihp; p1 = *(const float4*)(ihp + 4);
    sB[0][kh + 0][rr] = p0.x; sB[0][kh + 1][rr] = p0.y; sB[0][kh + 2][rr] = p0.z; sB[0][kh + 3][rr] = p0.w;
    sB[0][kh + 4][rr] = p1.x; sB[0][kh + 5][rr] = p1.y; sB[0][kh + 6][rr] = p1.z; sB[0][kh + 7][rr] = p1.w;
    p0 = *(const float4*)(ihp + 16); p1 = *(const float4*)(ihp + 20);
    __syncthreads();

    int a0 = (tid >> 5) * 2;
    int r0 = (tid & 31) * 4;
    float acc[2][4] = {};

    for (int kc = 0; kc < 20; kc++) {
        int cur = kc & 1;
        if (kc + 1 < 20) {
            int nb = cur ^ 1;
            sB[nb][kh + 0][rr] = p0.x; sB[nb][kh + 1][rr] = p0.y; sB[nb][kh + 2][rr] = p0.z; sB[nb][kh + 3][rr] = p0.w;
            sB[nb][kh + 4][rr] = p1.x; sB[nb][kh + 5][rr] = p1.y; sB[nb][kh + 6][rr] = p1.z; sB[nb][kh + 7][rr] = p1.w;
        }
        if (kc + 2 < 20) {
            int c2 = kc + 2;
            const float* sp = (c2 < 12) ? (ihp + c2 * 16) : (hhp + (c2 - 12) * 16);
            p0 = *(const float4*)sp; p1 = *(const float4*)(sp + 4);
        }
        // inner 16 k with 2-stage register pipeline
        float2 xa = *(const float2*)&sX[kc * 16][a0];
        float4 wb = *(const float4*)&sB[cur][0][r0];
        #pragma unroll
        for (int k = 0; k < 16; k++) {
            float2 xn; float4 wn;
            if (k < 15) {
                xn = *(const float2*)&sX[kc * 16 + k + 1][a0];
                wn = *(const float4*)&sB[cur][k + 1][r0];
            }
            acc[0][0] += xa.x * wb.x; acc[0][1] += xa.x * wb.y;
            acc[0][2] += xa.x * wb.z; acc[0][3] += xa.x * wb.w;
            acc[1][0] += xa.y * wb.x; acc[1][1] += xa.y * wb.y;
            acc[1][2] += xa.y * wb.z; acc[1][3] += xa.y * wb.w;
            if (k < 15) { xa = xn; wb = wn; }
        }
        __syncthreads();
    }

    // biases + stage gates
    #pragma unroll
    for (int j = 0; j < 4; j++) {
        int r = r0 + j;
        int gr2 = h0 + (r & 31) + ((r >> 5) * HH);
        float bias = b_ih[gr2] + b_hh[gr2];
        sG[a0 + 0][r] = acc[0][j] + bias;
        sG[a0 + 1][r] = acc[1][j] + bias;
    }
    __syncthreads();

    // LSTM pointwise
    int hc = tid & 31;
    #pragma unroll
    for (int q = 0; q < 2; q++) {
        int a  = (tid >> 5) + q * 8;
        int ga = A0 + a;
        float iv = sG[a][hc],      fv = sG[a][32 + hc];
        float gv = sG[a][64 + hc], ov = sG[a][96 + hc];
        int idx = ga * HH + h0 + hc;
        float c_old = g_c[idx];
        float si = 1.f / (1.f + __expf(-iv));
        float sf = 1.f / (1.f + __expf(-fv));
        float so = 1.f / (1.f + __expf(-ov));
        float cn = sf * c_old + si * tanhf(gv);
        float hn = so * tanhf(cn);
        g_c[idx]   = cn;
        h_out[idx] = hn;
    }
}

// ---------------- K4: decoder output projection + position advance ----------------
__global__ void __launch_bounds__(256) k4_out(
    int hbuf_new, int s, float* __restrict__ out,
    const float* __restrict__ Wout, const float* __restrict__ bout)
{
    int gid = blockIdx.x * 256 + threadIdx.x;        // 0..1023
    int agent = gid >> 1, coord = gid & 1;
    const float* __restrict__ h_new = g_h[hbuf_new];
    const float* __restrict__ pos_cur = g_slot[s & 1];
    float* __restrict__ slot_next = g_slot[(s + 1) & 1];

    const float4* h4 = (const float4*)&h_new[agent * HH];
    const float4* w4 = (const float4*)&Wout[coord * HH];
    float acc = 0.f;
    #pragma unroll
    for (int k = 0; k < HH / 4; k++) {
        float4 a = h4[k], b = w4[k];
        acc += a.x * b.x + a.y * b.y + a.z * b.z + a.w * b.w;
    }
    float v = pos_cur[agent * 2 + coord] + acc + bout[coord];
    slot_next[agent * 2 + coord] = v;
    out[(s * NN + agent) * 2 + coord] = v;
}

// ---------------- host launcher ----------------
extern "C" void kernel_launch(void* const* d_in, const int* in_sizes, int n_in,
                              void* d_out, int out_size) {
    const float* obs   = (const float*)d_in[0];
    const float* Wposw = (const float*)d_in[1];
    const float* bposw = (const float*)d_in[2];
    const float* Wpool = (const float*)d_in[3];
    const float* bpool = (const float*)d_in[4];
    const float* Wihe  = (const float*)d_in[5];
    const float* bihe  = (const float*)d_in[6];
    const float* Whhe  = (const float*)d_in[7];
    const float* bhhe  = (const float*)d_in[8];
    const float* Wihd  = (const float*)d_in[9];
    const float* bihd  = (const float*)d_in[10];
    const float* Whhd  = (const float*)d_in[11];
    const float* bhhd  = (const float*)d_in[12];
    const float* Woutw = (const float*)d_in[13];
    const float* boutw = (const float*)d_in[14];
    float* out = (float*)d_out;
    int np = out_size / (NN * 2);

    k0_setup<<<256, 256>>>(obs);

    int q = 0;
    // encoder: t = 1..7, pos = obs[t], prev = obs[t-1]
    for (int t = 1; t < TT; t++, q++) {
        int hb = q & 1;
        k1_pool<<<256, 128>>>(hb, 0, t);
        k2_soc<<<dim3(8, 4, KSP), 256>>>(Wpool);
        k3_lstm<<<dim3(32, 4), 256>>>(hb, 0, t, t - 1,
                                      Wihe, bihe, Whhe, bhhe, Wposw, bposw, bpool);
    }
    // decoder: s = 0..np-1, pos = slot[s&1], prev = slot[(s+1)&1]
    for (int s = 0; s < np; s++, q++) {
        int hb = q & 1;
        k1_pool<<<256, 128>>>(hb, 1, s & 1);
        k2_soc<<<dim3(8, 4, KSP), 256>>>(Wpool);
        k3_lstm<<<dim3(32, 4), 256>>>(hb, 1, s & 1, (s + 1) & 1,
                                      Wihd, bihd, Whhd, bhhd, Wposw, bposw, bpool);
        k4_out<<<4, 256>>>(hb ^ 1, s, out, Woutw, boutw);
    }
    (void)in_sizes; (void)n_in;
}

// round 7
// speedup vs baseline: 2.1783x; 1.0946x over previous
#include <cuda_runtime.h>
#include <math.h>
#include <float.h>

#define TT 8
#define NN 512
#define EE 64
#define HH 128
#define NC 16          // G*G
#define PP 128
#define KX 192         // E + P
#define KG 320         // KX + H
#define KSP 8          // K-splits for soc GEMM

// ---------------- packed f32x2 helpers ----------------
__device__ __forceinline__ unsigned long long ffma2(unsigned long long a,
                                                    unsigned long long b,
                                                    unsigned long long c) {
    unsigned long long d;
    asm("fma.rn.f32x2 %0, %1, %2, %3;" : "=l"(d) : "l"(a), "l"(b), "l"(c));
    return d;
}
__device__ __forceinline__ unsigned long long pack2(float x, float y) {
    unsigned long long d;
    asm("mov.b64 %0, {%1, %2};" : "=l"(d) : "f"(x), "f"(y));
    return d;
}
__device__ __forceinline__ float2 upk(unsigned long long v) {
    float2 f;
    asm("mov.b64 {%0, %1}, %2;" : "=f"(f.x), "=f"(f.y) : "l"(v));
    return f;
}

// ---------------- persistent scratch ----------------
__device__ float g_obs[TT * NN * 2];
__device__ float g_h[2][NN * HH];
__device__ float g_c[NN * HH];
__device__ float g_grid[NN * NC * HH];
__device__ float g_part[KSP][NN * PP];
__device__ float g_slot[2][NN * 2];

// ---------------- K0: impute + zero state ----------------
__global__ void k0_setup(const float* __restrict__ obs_in) {
    int gid = blockIdx.x * blockDim.x + threadIdx.x;
    int nth = gridDim.x * blockDim.x;
    for (int i = gid; i < NN * HH; i += nth) {
        g_h[0][i] = 0.f; g_h[1][i] = 0.f; g_c[i] = 0.f;
    }
    if (gid < NN) {
        int n = gid;
        unsigned fm = 0; int first = 0; int ffound = 0;
        for (int t = 0; t < TT; t++) {
            float x = obs_in[(t * NN + n) * 2];
            float y = obs_in[(t * NN + n) * 2 + 1];
            if (isfinite(x) && isfinite(y)) {
                fm |= (1u << t);
                if (!ffound) { first = t; ffound = 1; }
            }
        }
        int last = -1;
        for (int t = 0; t < TT; t++) {
            if (fm & (1u << t)) last = t;
            int take = (last >= 0) ? last : first;
            float wx = 0.f, wy = 0.f;
            if (fm) {
                wx = obs_in[(take * NN + n) * 2];
                wy = obs_in[(take * NN + n) * 2 + 1];
            }
            g_obs[(t * NN + n) * 2]     = wx;
            g_obs[(t * NN + n) * 2 + 1] = wy;
        }
        float sx = g_obs[((TT - 1) * NN + n) * 2];
        float sy = g_obs[((TT - 1) * NN + n) * 2 + 1];
        g_slot[0][n * 2] = sx; g_slot[0][n * 2 + 1] = sy;
        g_slot[1][n * 2] = sx; g_slot[1][n * 2 + 1] = sy;
    }
}

// ---------------- K1: social pooling (grid-cell max) ----------------
__global__ void __launch_bounds__(128) k1_pool(int hbuf, int pos_is_slot, int pos_idx) {
    __shared__ float spos[NN * 2];
    __shared__ unsigned char scid[NN * 2];
    __shared__ float sg[2][NC * HH];

    const float* __restrict__ h_in = g_h[hbuf];
    const float* __restrict__ pos  = pos_is_slot ? g_slot[pos_idx] : (g_obs + pos_idx * NN * 2);

    int tid  = threadIdx.x;
    int base = blockIdx.x * 2;

    for (int i = tid; i < NN * 2; i += 128) spos[i] = pos[i];
    for (int i = tid; i < 2 * NC * HH; i += 128) ((float*)sg)[i] = -FLT_MAX;
    __syncthreads();

    for (int it = tid; it < NN * 2; it += 128) {
        int a = it & 1, j = it >> 1;
        int i = base + a;
        float rx = spos[j * 2]     - spos[i * 2];
        float ry = spos[j * 2 + 1] - spos[i * 2 + 1];
        unsigned char cid = 255;
        if (j != i && fabsf(rx) <= 1.0f && fabsf(ry) <= 1.0f) {
            int gx = (int)floorf((rx + 1.0f) * 2.0f);
            int gy = (int)floorf((ry + 1.0f) * 2.0f);
            gx = min(max(gx, 0), 3); gy = min(max(gy, 0), 3);
            cid = (unsigned char)(gx * 4 + gy);
        }
        scid[it] = cid;
    }
    __syncthreads();

    const uchar2* sc2 = (const uchar2*)scid;
    float bufA[8], bufB[8];
    #pragma unroll
    for (int q = 0; q < 8; q++) bufA[q] = h_in[q * HH + tid];

    for (int jb = 0; jb < NN; jb += 8) {
        #pragma unroll
        for (int q = 0; q < 8; q++)
            bufB[q] = h_in[(((jb + 8 + q) & (NN - 1)) * HH) + tid];
        #pragma unroll
        for (int q = 0; q < 8; q++) {
            uchar2 c2 = sc2[jb + q];
            float hv = bufA[q];
            if (c2.x != 255) { float* p = &sg[0][c2.x * HH + tid]; *p = fmaxf(*p, hv); }
            if (c2.y != 255) { float* p = &sg[1][c2.y * HH + tid]; *p = fmaxf(*p, hv); }
        }
        #pragma unroll
        for (int q = 0; q < 8; q++) bufA[q] = bufB[q];
    }
    __syncthreads();

    #pragma unroll
    for (int a = 0; a < 2; a++) {
        #pragma unroll
        for (int c = 0; c < NC; c++) {
            float v = sg[a][c * HH + tid];
            g_grid[(base + a) * (NC * HH) + c * HH + tid] = (v == -FLT_MAX) ? 0.f : v;
        }
    }
}

// ---------------- K2: soc GEMM partials: grid[512,2048] @ W_pool^T ----------------
// grid(8 M, 2 N, 8 Ksplit) = 128 blocks x 256 thr; tile 64x64, K=256/split; 4x4 FFMA2.
__global__ void __launch_bounds__(256) k2_soc(const float* __restrict__ Wp) {
    __shared__ __align__(16) float sA[2][64][36];   // [agent][k] row-major, padded
    __shared__ __align__(16) float sB[2][32][64];   // [k][channel]

    int tid = threadIdx.x;
    int A0  = blockIdx.x * 64;
    int C0  = blockIdx.y * 64;
    int KB0 = blockIdx.z * 256;

    int la  = tid >> 2, lka = (tid & 3) * 8;        // A loader
    int cb  = tid & 63, lkb = (tid >> 6) * 8;       // B loader (conflict-free stores)
    const float* Asrc = &g_grid[(A0 + la) * (NC * HH) + KB0 + lka];
    const float* Bsrc = &Wp[(C0 + cb) * (NC * HH) + KB0 + lkb];

    int a0 = (tid >> 4) * 4;
    int c0 = (tid & 15) * 4;

    float4 ra0, ra1, rb0, rb1;
#define K2_LD(c) { const float* sa_ = Asrc + (c) * 32; const float* sb_ = Bsrc + (c) * 32; \
    ra0 = ((const float4*)sa_)[0]; ra1 = ((const float4*)sa_)[1]; \
    rb0 = ((const float4*)sb_)[0]; rb1 = ((const float4*)sb_)[1]; }
#define K2_ST(buf) { \
    *(float4*)&sA[buf][la][lka] = ra0; *(float4*)&sA[buf][la][lka + 4] = ra1; \
    float* b_ = &sB[buf][lkb][cb]; \
    b_[0*64] = rb0.x; b_[1*64] = rb0.y; b_[2*64] = rb0.z; b_[3*64] = rb0.w; \
    b_[4*64] = rb1.x; b_[5*64] = rb1.y; b_[6*64] = rb1.z; b_[7*64] = rb1.w; }

    K2_LD(0); K2_ST(0); K2_LD(1);
    __syncthreads();

    unsigned long long acc[4][2] = {{0ull,0ull},{0ull,0ull},{0ull,0ull},{0ull,0ull}};

    for (int kc = 0; kc < 8; kc++) {
        int cur = kc & 1;
        if (kc + 1 < 8) K2_ST(cur ^ 1);
        if (kc + 2 < 8) K2_LD(kc + 2);
        #pragma unroll
        for (int k = 0; k < 32; k++) {
            ulonglong2 bv = *(const ulonglong2*)&sB[cur][k][c0];
            float x0 = sA[cur][a0 + 0][k];
            float x1 = sA[cur][a0 + 1][k];
            float x2 = sA[cur][a0 + 2][k];
            float x3 = sA[cur][a0 + 3][k];
            unsigned long long xp;
            xp = pack2(x0, x0); acc[0][0] = ffma2(xp, bv.x, acc[0][0]); acc[0][1] = ffma2(xp, bv.y, acc[0][1]);
            xp = pack2(x1, x1); acc[1][0] = ffma2(xp, bv.x, acc[1][0]); acc[1][1] = ffma2(xp, bv.y, acc[1][1]);
            xp = pack2(x2, x2); acc[2][0] = ffma2(xp, bv.x, acc[2][0]); acc[2][1] = ffma2(xp, bv.y, acc[2][1]);
            xp = pack2(x3, x3); acc[3][0] = ffma2(xp, bv.x, acc[3][0]); acc[3][1] = ffma2(xp, bv.y, acc[3][1]);
        }
        __syncthreads();
    }

    float* dst = g_part[blockIdx.z];
    #pragma unroll
    for (int i = 0; i < 4; i++) {
        *(unsigned long long*)&dst[(A0 + a0 + i) * PP + C0 + c0]     = acc[i][0];
        *(unsigned long long*)&dst[(A0 + a0 + i) * PP + C0 + c0 + 2] = acc[i][1];
    }
#undef K2_LD
#undef K2_ST
}

// ---------------- K3: fused x-build + gate GEMM + LSTM pointwise ----------------
// grid(32 agent-tiles, 4 h-tiles) x 256 thr; 2-way K-split, 4x4 FFMA2 blocking.
__global__ void __launch_bounds__(256) k3_lstm(
    int hbuf, int pos_is_slot, int pos_idx, int prev_idx,
    const float* __restrict__ W_ih, const float* __restrict__ b_ih,
    const float* __restrict__ W_hh, const float* __restrict__ b_hh,
    const float* __restrict__ Wpos, const float* __restrict__ bpos,
    const float* __restrict__ bpool)
{
    __shared__ __align__(16) float sX[KG][16];          // 20KB (aliased after GEMM)
    __shared__ __align__(16) float sB[2][2][8][128];    // 16KB, [buf][kgrp][k][row]

    const float* __restrict__ h_in  = g_h[hbuf];
    float*       __restrict__ h_out = g_h[hbuf ^ 1];
    const float* __restrict__ pos  = pos_is_slot ? g_slot[pos_idx]  : (g_obs + pos_idx  * NN * 2);
    const float* __restrict__ prev = pos_is_slot ? g_slot[prev_idx] : (g_obs + prev_idx * NN * 2);

    int tid = threadIdx.x;
    int A0  = blockIdx.x * 16;
    int h0  = blockIdx.y * 32;

    // build x = [relu(vel@Wpos^T+b) | relu(sum(part)+bpool) | h_in]
    for (int it = tid; it < 16 * KG; it += 256) {
        int a = it / KG, k = it - a * KG;
        int ga = A0 + a;
        float v;
        if (k < EE) {
            float vx = pos[ga * 2]     - prev[ga * 2];
            float vy = pos[ga * 2 + 1] - prev[ga * 2 + 1];
            v = fmaxf(Wpos[k * 2] * vx + Wpos[k * 2 + 1] * vy + bpos[k], 0.f);
        } else if (k < KX) {
            int c = k - EE;
            float s = bpool[c];
            #pragma unroll
            for (int p = 0; p < KSP; p++) s += g_part[p][ga * PP + c];
            v = fmaxf(s, 0.f);
        } else {
            v = h_in[ga * HH + (k - KX)];
        }
        sX[k][a] = v;
    }

    int kg = tid >> 7;          // k-group 0/1 (k in [kg*160, kg*160+160))
    int t  = tid & 127;
    int rr = t;                 // gate row within tile (0..127)
    int grow = h0 + (rr & 31) + ((rr >> 5) * HH);
    const float* ihrow = W_ih + grow * KX;
    const float* hhrow = W_hh + grow * HH;

    float4 w0, w1;
#define K3_LD(c) { int kb_ = kg * 160 + (c) * 8; \
    const float* s_ = (kb_ < KX) ? (ihrow + kb_) : (hhrow + (kb_ - KX)); \
    w0 = ((const float4*)s_)[0]; w1 = ((const float4*)s_)[1]; }
#define K3_ST(buf) { float* b_ = &sB[buf][kg][0][rr]; \
    b_[0*128] = w0.x; b_[1*128] = w0.y; b_[2*128] = w0.z; b_[3*128] = w0.w; \
    b_[4*128] = w1.x; b_[5*128] = w1.y; b_[6*128] = w1.z; b_[7*128] = w1.w; }

    K3_LD(0); K3_ST(0); K3_LD(1);
    __syncthreads();

    int ag = t >> 5, rg = t & 31;
    int a0 = ag * 4, r0 = rg * 4;
    unsigned long long acc[4][2] = {{0ull,0ull},{0ull,0ull},{0ull,0ull},{0ull,0ull}};

    for (int kc = 0; kc < 20; kc++) {
        int cur = kc & 1;
        if (kc + 1 < 20) K3_ST(cur ^ 1);
        if (kc + 2 < 20) K3_LD(kc + 2);
        int kb = kg * 160 + kc * 8;
        #pragma unroll
        for (int k = 0; k < 8; k++) {
            float4 xv = *(const float4*)&sX[kb + k][a0];          // broadcast
            ulonglong2 wv = *(const ulonglong2*)&sB[cur][kg][k][r0];
            unsigned long long xp;
            xp = pack2(xv.x, xv.x); acc[0][0] = ffma2(xp, wv.x, acc[0][0]); acc[0][1] = ffma2(xp, wv.y, acc[0][1]);
            xp = pack2(xv.y, xv.y); acc[1][0] = ffma2(xp, wv.x, acc[1][0]); acc[1][1] = ffma2(xp, wv.y, acc[1][1]);
            xp = pack2(xv.z, xv.z); acc[2][0] = ffma2(xp, wv.x, acc[2][0]); acc[2][1] = ffma2(xp, wv.y, acc[2][1]);
            xp = pack2(xv.w, xv.w); acc[3][0] = ffma2(xp, wv.x, acc[3][0]); acc[3][1] = ffma2(xp, wv.y, acc[3][1]);
        }
        __syncthreads();
    }
#undef K3_LD
#undef K3_ST

    // cross-group reduce + bias + gate staging (alias dead sX region)
    float* sxf = &sX[0][0];
    float (*sRed)[128] = reinterpret_cast<float(*)[128]>(sxf);           // 16x128
    float (*sG)[132]   = reinterpret_cast<float(*)[132]>(sxf + 2048);    // 16x132

    if (kg == 1) {
        #pragma unroll
        for (int i = 0; i < 4; i++) {
            *(unsigned long long*)&sRed[a0 + i][r0]     = acc[i][0];
            *(unsigned long long*)&sRed[a0 + i][r0 + 2] = acc[i][1];
        }
    }
    __syncthreads();
    if (kg == 0) {
        #pragma unroll
        for (int i = 0; i < 4; i++) {
            float2 pa = upk(acc[i][0]), pb = upk(acc[i][1]);
            float2 qa = *(float2*)&sRed[a0 + i][r0];
            float2 qb = *(float2*)&sRed[a0 + i][r0 + 2];
            float v[4] = {pa.x + qa.x, pa.y + qa.y, pb.x + qb.x, pb.y + qb.y};
            #pragma unroll
            for (int j = 0; j < 4; j++) {
                int r = r0 + j;
                int gr = h0 + (r & 31) + ((r >> 5) * HH);
                sG[a0 + i][r] = v[j] + b_ih[gr] + b_hh[gr];
            }
        }
    }
    __syncthreads();

    // LSTM pointwise
    int hc = tid & 31;
    #pragma unroll
    for (int q = 0; q < 2; q++) {
        int a  = (tid >> 5) + q * 8;
        int ga = A0 + a;
        float iv = sG[a][hc],      fv = sG[a][32 + hc];
        float gv = sG[a][64 + hc], ov = sG[a][96 + hc];
        int idx = ga * HH + h0 + hc;
        float c_old = g_c[idx];
        float si = 1.f / (1.f + __expf(-iv));
        float sf = 1.f / (1.f + __expf(-fv));
        float so = 1.f / (1.f + __expf(-ov));
        float cn = sf * c_old + si * tanhf(gv);
        float hn = so * tanhf(cn);
        g_c[idx]   = cn;
        h_out[idx] = hn;
    }
}

// ---------------- K4: decoder output projection + position advance ----------------
__global__ void __launch_bounds__(256) k4_out(
    int hbuf_new, int s, float* __restrict__ out,
    const float* __restrict__ Wout, const float* __restrict__ bout)
{
    int gid = blockIdx.x * 256 + threadIdx.x;
    int agent = gid >> 1, coord = gid & 1;
    const float* __restrict__ h_new = g_h[hbuf_new];
    const float* __restrict__ pos_cur = g_slot[s & 1];
    float* __restrict__ slot_next = g_slot[(s + 1) & 1];

    const float4* h4 = (const float4*)&h_new[agent * HH];
    const float4* w4 = (const float4*)&Wout[coord * HH];
    float acc = 0.f;
    #pragma unroll
    for (int k = 0; k < HH / 4; k++) {
        float4 a = h4[k], b = w4[k];
        acc += a.x * b.x + a.y * b.y + a.z * b.z + a.w * b.w;
    }
    float v = pos_cur[agent * 2 + coord] + acc + bout[coord];
    slot_next[agent * 2 + coord] = v;
    out[(s * NN + agent) * 2 + coord] = v;
}

// ---------------- host launcher ----------------
extern "C" void kernel_launch(void* const* d_in, const int* in_sizes, int n_in,
                              void* d_out, int out_size) {
    const float* obs   = (const float*)d_in[0];
    const float* Wposw = (const float*)d_in[1];
    const float* bposw = (const float*)d_in[2];
    const float* Wpool = (const float*)d_in[3];
    const float* bpool = (const float*)d_in[4];
    const float* Wihe  = (const float*)d_in[5];
    const float* bihe  = (const float*)d_in[6];
    const float* Whhe  = (const float*)d_in[7];
    const float* bhhe  = (const float*)d_in[8];
    const float* Wihd  = (const float*)d_in[9];
    const float* bihd  = (const float*)d_in[10];
    const float* Whhd  = (const float*)d_in[11];
    const float* bhhd  = (const float*)d_in[12];
    const float* Woutw = (const float*)d_in[13];
    const float* boutw = (const float*)d_in[14];
    float* out = (float*)d_out;
    int np = out_size / (NN * 2);

    k0_setup<<<256, 256>>>(obs);

    int q = 0;
    for (int t = 1; t < TT; t++, q++) {
        int hb = q & 1;
        k1_pool<<<256, 128>>>(hb, 0, t);
        k2_soc<<<dim3(8, 2, KSP), 256>>>(Wpool);
        k3_lstm<<<dim3(32, 4), 256>>>(hb, 0, t, t - 1,
                                      Wihe, bihe, Whhe, bhhe, Wposw, bposw, bpool);
    }
    for (int s = 0; s < np; s++, q++) {
        int hb = q & 1;
        k1_pool<<<256, 128>>>(hb, 1, s & 1);
        k2_soc<<<dim3(8, 2, KSP), 256>>>(Wpool);
        k3_lstm<<<dim3(32, 4), 256>>>(hb, 1, s & 1, (s + 1) & 1,
                                      Wihd, bihd, Whhd, bhhd, Wposw, bposw, bpool);
        k4_out<<<4, 256>>>(hb ^ 1, s, out, Woutw, boutw);
    }
    (void)in_sizes; (void)n_in;
}